// round 1
// baseline (speedup 1.0000x reference)
#include <cuda_runtime.h>
#include <cstddef>

#define E_DIM 1024
#define T_SEQ 1024
#define BATCH 4
#define N_HEAD 16
#define D_K 64
#define SCALE 0.125f
#define WEPS 1e-5f

// Scratch buffers (allocation-free rule: __device__ globals)
__device__ float g_Qp[BATCH * T_SEQ * E_DIM];
__device__ float g_Kp[BATCH * T_SEQ * E_DIM];
__device__ float g_Vp[BATCH * T_SEQ * E_DIM];
__device__ float g_Ctx[BATCH * T_SEQ * E_DIM];

// ---------------------------------------------------------------------------
// GEMM: C[M,N] = A[M,K] @ B[N,K]^T + bias[N]   (both A and B are K-contiguous)
// BM=128, BN=64, BK=8, 256 threads, 8x4 microtile per thread.
// ---------------------------------------------------------------------------
#define BM 128
#define BN 64
#define BK 8

__global__ __launch_bounds__(256) void gemm_nt_bias(
    const float* __restrict__ A, const float* __restrict__ B,
    const float* __restrict__ bias, float* __restrict__ C,
    int M, int N, int K)
{
    __shared__ float As[BK][BM];
    __shared__ float Bs[BK][BN];

    const int tid = threadIdx.x;
    const int m0 = blockIdx.y * BM;
    const int n0 = blockIdx.x * BN;
    const int tr = tid >> 4;   // 0..15 -> rows tr*8 + i
    const int tc = tid & 15;   // 0..15 -> cols tc*4 + j

    // Global-load mapping
    const int arow = tid >> 1;            // 0..127
    const int ak4  = (tid & 1) * 4;       // 0 or 4
    const int brow = tid >> 1;            // valid for tid < 128
    const int bk4  = (tid & 1) * 4;

    const float* Aptr = A + (size_t)(m0 + arow) * K + ak4;
    const float* Bptr = B + (size_t)(n0 + (tid < 128 ? brow : 0)) * K + bk4;

    float acc[8][4];
#pragma unroll
    for (int i = 0; i < 8; i++)
#pragma unroll
        for (int j = 0; j < 4; j++) acc[i][j] = 0.f;

    float4 av = *(const float4*)(Aptr);
    float4 bv = make_float4(0.f, 0.f, 0.f, 0.f);
    if (tid < 128) bv = *(const float4*)(Bptr);

    for (int kt = 0; kt < K; kt += BK) {
        __syncthreads();
        As[ak4 + 0][arow] = av.x;
        As[ak4 + 1][arow] = av.y;
        As[ak4 + 2][arow] = av.z;
        As[ak4 + 3][arow] = av.w;
        if (tid < 128) {
            Bs[bk4 + 0][brow] = bv.x;
            Bs[bk4 + 1][brow] = bv.y;
            Bs[bk4 + 2][brow] = bv.z;
            Bs[bk4 + 3][brow] = bv.w;
        }
        __syncthreads();

        if (kt + BK < K) {
            av = *(const float4*)(Aptr + kt + BK);
            if (tid < 128) bv = *(const float4*)(Bptr + kt + BK);
        }

#pragma unroll
        for (int kk = 0; kk < BK; kk++) {
            float4 a0 = *(const float4*)&As[kk][tr * 8];
            float4 a1 = *(const float4*)&As[kk][tr * 8 + 4];
            float4 b0 = *(const float4*)&Bs[kk][tc * 4];
            float a[8] = {a0.x, a0.y, a0.z, a0.w, a1.x, a1.y, a1.z, a1.w};
            float b[4] = {b0.x, b0.y, b0.z, b0.w};
#pragma unroll
            for (int i = 0; i < 8; i++)
#pragma unroll
                for (int j = 0; j < 4; j++) acc[i][j] += a[i] * b[j];
        }
    }

    float4 bb = *(const float4*)&bias[n0 + tc * 4];
#pragma unroll
    for (int i = 0; i < 8; i++) {
        int m = m0 + tr * 8 + i;
        float4 out;
        out.x = acc[i][0] + bb.x;
        out.y = acc[i][1] + bb.y;
        out.z = acc[i][2] + bb.z;
        out.w = acc[i][3] + bb.w;
        *(float4*)&C[(size_t)m * N + n0 + tc * 4] = out;
    }
}

// ---------------------------------------------------------------------------
// Flash-style attention: 1 CTA per (b, h, 64-row q tile); 64-key tiles.
// 8 warps, each owns 8 q rows. Lane owns key/dk columns {lane, lane+32}.
// Online softmax; P staged through SMEM for the PV product.
// ---------------------------------------------------------------------------
#define ATT_PAD 2
#define ATT_STRIDE (64 + ATT_PAD)
// smem floats: Qs + Ks + Vs (3*64*66) + Ps (8*8*66) + ws (64)
#define ATTN_SMEM_FLOATS (3 * 64 * ATT_STRIDE + 8 * 8 * ATT_STRIDE + 64)
#define ATTN_SMEM_BYTES (ATTN_SMEM_FLOATS * 4)

__global__ __launch_bounds__(256) void attn_kernel(
    const float* __restrict__ Qp, const float* __restrict__ Kp,
    const float* __restrict__ Vp, const float* __restrict__ W,
    float* __restrict__ Ctx)
{
    extern __shared__ float sm[];
    float (*Qs)[ATT_STRIDE] = (float(*)[ATT_STRIDE])sm;
    float (*Ks)[ATT_STRIDE] = (float(*)[ATT_STRIDE])(sm + 64 * ATT_STRIDE);
    float (*Vs)[ATT_STRIDE] = (float(*)[ATT_STRIDE])(sm + 2 * 64 * ATT_STRIDE);
    float (*Ps)[8][ATT_STRIDE] = (float(*)[8][ATT_STRIDE])(sm + 3 * 64 * ATT_STRIDE);
    float* ws = sm + 3 * 64 * ATT_STRIDE + 8 * 8 * ATT_STRIDE;

    const int tid  = threadIdx.x;
    const int warp = tid >> 5;
    const int lane = tid & 31;
    const int qt = blockIdx.x, h = blockIdx.y, b = blockIdx.z;
    const int r0 = warp * 8;

    // Load Q tile [64 x 64]
    const float* qbase = Qp + ((size_t)(b * T_SEQ + qt * 64)) * E_DIM + h * D_K;
    for (int i = tid; i < 64 * 16; i += 256) {
        int r = i >> 4, c4 = (i & 15) << 2;
        float4 v = *(const float4*)(qbase + (size_t)r * E_DIM + c4);
        Qs[r][c4] = v.x; Qs[r][c4 + 1] = v.y; Qs[r][c4 + 2] = v.z; Qs[r][c4 + 3] = v.w;
    }

    float o0[8], o1[8], mrun[8], lrun[8];
#pragma unroll
    for (int r = 0; r < 8; r++) { o0[r] = 0.f; o1[r] = 0.f; mrun[r] = -1e30f; lrun[r] = 0.f; }

    for (int kt = 0; kt < T_SEQ / 64; kt++) {
        __syncthreads();   // previous tile fully consumed (and Qs ready on iter 0)
        const float* kbase = Kp + ((size_t)(b * T_SEQ + kt * 64)) * E_DIM + h * D_K;
        const float* vbase = Vp + ((size_t)(b * T_SEQ + kt * 64)) * E_DIM + h * D_K;
        for (int i = tid; i < 64 * 16; i += 256) {
            int r = i >> 4, c4 = (i & 15) << 2;
            float4 kv = *(const float4*)(kbase + (size_t)r * E_DIM + c4);
            Ks[r][c4] = kv.x; Ks[r][c4 + 1] = kv.y; Ks[r][c4 + 2] = kv.z; Ks[r][c4 + 3] = kv.w;
            float4 vv = *(const float4*)(vbase + (size_t)r * E_DIM + c4);
            Vs[r][c4] = vv.x; Vs[r][c4 + 1] = vv.y; Vs[r][c4 + 2] = vv.z; Vs[r][c4 + 3] = vv.w;
        }
        if (tid < 64) ws[tid] = W[b * T_SEQ + kt * 64 + tid];
        __syncthreads();

        // S = Q K^T for this warp's 8 rows; lane covers keys {lane, lane+32}
        float s0[8], s1[8];
#pragma unroll
        for (int r = 0; r < 8; r++) { s0[r] = 0.f; s1[r] = 0.f; }
#pragma unroll 4
        for (int d2 = 0; d2 < 32; d2++) {
            float2 k0 = *(const float2*)&Ks[lane][d2 * 2];
            float2 k1 = *(const float2*)&Ks[lane + 32][d2 * 2];
#pragma unroll
            for (int r = 0; r < 8; r++) {
                float2 q = *(const float2*)&Qs[r0 + r][d2 * 2];
                s0[r] += q.x * k0.x + q.y * k0.y;
                s1[r] += q.x * k1.x + q.y * k1.y;
            }
        }

        // weight mask + scale: energy = where(w < eps, -inf, (qk*SCALE)*(w*w))
        float w0 = ws[lane], w1 = ws[lane + 32];
        float f0 = SCALE * w0 * w0, f1 = SCALE * w1 * w1;
        bool msk0 = (w0 < WEPS), msk1 = (w1 < WEPS);
#pragma unroll
        for (int r = 0; r < 8; r++) {
            s0[r] = msk0 ? -1e30f : s0[r] * f0;
            s1[r] = msk1 ? -1e30f : s1[r] * f1;
        }

        // online softmax per row
#pragma unroll
        for (int r = 0; r < 8; r++) {
            float mt = fmaxf(s0[r], s1[r]);
#pragma unroll
            for (int off = 16; off; off >>= 1)
                mt = fmaxf(mt, __shfl_xor_sync(0xffffffffu, mt, off));
            float mnew = fmaxf(mrun[r], mt);
            float p0 = (s0[r] < -1e29f) ? 0.f : __expf(s0[r] - mnew);
            float p1 = (s1[r] < -1e29f) ? 0.f : __expf(s1[r] - mnew);
            float alpha = __expf(mrun[r] - mnew);
            float pt = p0 + p1;
#pragma unroll
            for (int off = 16; off; off >>= 1)
                pt += __shfl_xor_sync(0xffffffffu, pt, off);
            lrun[r] = lrun[r] * alpha + pt;
            o0[r] *= alpha;
            o1[r] *= alpha;
            mrun[r] = mnew;
            Ps[warp][r][lane] = p0;
            Ps[warp][r][lane + 32] = p1;
        }
        __syncwarp();

        // O += P @ V   (lane covers dk columns {lane, lane+32})
#pragma unroll 4
        for (int c2 = 0; c2 < 32; c2++) {
            int c = c2 * 2;
            float v00 = Vs[c][lane],     v01 = Vs[c][lane + 32];
            float v10 = Vs[c + 1][lane], v11 = Vs[c + 1][lane + 32];
#pragma unroll
            for (int r = 0; r < 8; r++) {
                float2 p = *(const float2*)&Ps[warp][r][c];
                o0[r] += p.x * v00 + p.y * v10;
                o1[r] += p.x * v01 + p.y * v11;
            }
        }
    }

    float* obase = Ctx + ((size_t)(b * T_SEQ + qt * 64 + r0)) * E_DIM + h * D_K;
#pragma unroll
    for (int r = 0; r < 8; r++) {
        float inv = 1.f / lrun[r];
        obase[(size_t)r * E_DIM + lane]      = o0[r] * inv;
        obase[(size_t)r * E_DIM + lane + 32] = o1[r] * inv;
    }
}

// ---------------------------------------------------------------------------
extern "C" void kernel_launch(void* const* d_in, const int* in_sizes, int n_in,
                              void* d_out, int out_size)
{
    const float* q  = (const float*)d_in[0];
    const float* k  = (const float*)d_in[1];
    const float* v  = (const float*)d_in[2];
    const float* wt = (const float*)d_in[3];
    const float* Wq = (const float*)d_in[4];
    const float* bq = (const float*)d_in[5];
    const float* Wk = (const float*)d_in[6];
    const float* bk = (const float*)d_in[7];
    const float* Wv = (const float*)d_in[8];
    const float* bv = (const float*)d_in[9];
    const float* Wo = (const float*)d_in[10];
    const float* bo = (const float*)d_in[11];

    float *Qp, *Kp, *Vp, *Ctx;
    cudaGetSymbolAddress((void**)&Qp, g_Qp);
    cudaGetSymbolAddress((void**)&Kp, g_Kp);
    cudaGetSymbolAddress((void**)&Vp, g_Vp);
    cudaGetSymbolAddress((void**)&Ctx, g_Ctx);

    cudaFuncSetAttribute(attn_kernel, cudaFuncAttributeMaxDynamicSharedMemorySize,
                         ATTN_SMEM_BYTES);

    const int M = BATCH * T_SEQ;   // 4096
    const int N = E_DIM, K = E_DIM;
    dim3 gg(N / BN, M / BM);       // (16, 32)

    gemm_nt_bias<<<gg, 256>>>(q, Wq, bq, Qp, M, N, K);
    gemm_nt_bias<<<gg, 256>>>(k, Wk, bk, Kp, M, N, K);
    gemm_nt_bias<<<gg, 256>>>(v, Wv, bv, Vp, M, N, K);

    dim3 ga(T_SEQ / 64, N_HEAD, BATCH);  // (16, 16, 4)
    attn_kernel<<<ga, 256, ATTN_SMEM_BYTES>>>(Qp, Kp, Vp, wt, Ctx);

    gemm_nt_bias<<<gg, 256>>>(Ctx, Wo, bo, (float*)d_out, M, N, K);
}

// round 2
// speedup vs baseline: 1.4707x; 1.4707x over previous
#include <cuda_runtime.h>
#include <cuda_bf16.h>
#include <cstddef>

#define E_DIM 1024
#define T_SEQ 1024
#define BATCH 4
#define N_HEAD 16
#define D_K 64
#define SCALE 0.125f
#define WEPS 1e-5f

// Scratch buffers (allocation-free rule: __device__ globals)
__device__ float g_Qp[BATCH * T_SEQ * E_DIM];
__device__ float g_Kp[BATCH * T_SEQ * E_DIM];
__device__ float g_Vp[BATCH * T_SEQ * E_DIM];
__device__ float g_Ctx[BATCH * T_SEQ * E_DIM];

// ---------------------------------------------------------------------------
// PTX helpers
// ---------------------------------------------------------------------------
__device__ __forceinline__ unsigned smem_u32(const void* p) {
    return (unsigned)__cvta_generic_to_shared(p);
}
__device__ __forceinline__ void ldsm4(unsigned addr, unsigned& r0, unsigned& r1,
                                      unsigned& r2, unsigned& r3) {
    asm volatile("ldmatrix.sync.aligned.m8n8.x4.shared.b16 {%0,%1,%2,%3}, [%4];"
                 : "=r"(r0), "=r"(r1), "=r"(r2), "=r"(r3) : "r"(addr));
}
__device__ __forceinline__ void mma16816(float* c, unsigned a0, unsigned a1,
                                         unsigned a2, unsigned a3,
                                         unsigned b0, unsigned b1) {
    asm volatile(
        "mma.sync.aligned.m16n8k16.row.col.f32.bf16.bf16.f32 "
        "{%0,%1,%2,%3},{%4,%5,%6,%7},{%8,%9},{%0,%1,%2,%3};"
        : "+f"(c[0]), "+f"(c[1]), "+f"(c[2]), "+f"(c[3])
        : "r"(a0), "r"(a1), "r"(a2), "r"(a3), "r"(b0), "r"(b1));
}

// split fp32 -> bf16 hi + bf16 lo  (hi+lo reproduces x to ~2^-18 relative)
__device__ __forceinline__ void split_store(__nv_bfloat16* hi, __nv_bfloat16* lo,
                                            float4 v) {
    __nv_bfloat16 h;
    h = __float2bfloat16_rn(v.x); hi[0] = h; lo[0] = __float2bfloat16_rn(v.x - __bfloat162float(h));
    h = __float2bfloat16_rn(v.y); hi[1] = h; lo[1] = __float2bfloat16_rn(v.y - __bfloat162float(h));
    h = __float2bfloat16_rn(v.z); hi[2] = h; lo[2] = __float2bfloat16_rn(v.z - __bfloat162float(h));
    h = __float2bfloat16_rn(v.w); hi[3] = h; lo[3] = __float2bfloat16_rn(v.w - __bfloat162float(h));
}

// ---------------------------------------------------------------------------
// Tensor-core GEMM (bf16-split, fp32-equivalent precision):
//   C[M,N] = A[M,K] @ B[N,K]^T + bias[N]
// CTA 128x128, BK=16, 256 threads (8 warps, each 64x32).
// ---------------------------------------------------------------------------
#define GBM 128
#define GBN 128
#define GBK 16
#define GST 24   // smem row stride in bf16 elems (48B: conflict-free ldmatrix)

__global__ __launch_bounds__(256) void gemm_nt_bias_tc(
    const float* __restrict__ A, const float* __restrict__ B,
    const float* __restrict__ bias, float* __restrict__ C,
    int M, int N, int K)
{
    __shared__ __nv_bfloat16 sA[2][GBM][GST];   // [0]=hi, [1]=lo
    __shared__ __nv_bfloat16 sB[2][GBN][GST];

    const int tid = threadIdx.x;
    const int lane = tid & 31;
    const int warp = tid >> 5;
    const int mw = warp >> 2;      // 0..1
    const int nw = warp & 3;       // 0..3
    const int m0 = blockIdx.y * GBM;
    const int n0 = blockIdx.x * GBN;

    // Global load mapping: 2 float4 per thread per matrix per chunk.
    const int grow = tid >> 2;            // 0..63
    const int gcol = (tid & 3) * 4;       // 0,4,8,12
    const float* Ag = A + (size_t)(m0 + grow) * K + gcol;
    const float* Bg = B + (size_t)(n0 + grow) * K + gcol;

    float4 a0v = *(const float4*)(Ag);
    float4 a1v = *(const float4*)(Ag + (size_t)64 * K);
    float4 b0v = *(const float4*)(Bg);
    float4 b1v = *(const float4*)(Bg + (size_t)64 * K);

    float acc[4][4][4];
#pragma unroll
    for (int i = 0; i < 4; i++)
#pragma unroll
        for (int j = 0; j < 4; j++)
#pragma unroll
            for (int l = 0; l < 4; l++) acc[i][j][l] = 0.f;

    // Fragment smem addresses (fixed: single buffer).
    const int arow = mw * 64 + (lane & 15);
    const int akoff = (lane >> 4) * 8;
    unsigned aAddrH[4], aAddrL[4];
#pragma unroll
    for (int mf = 0; mf < 4; mf++) {
        aAddrH[mf] = smem_u32(&sA[0][arow + mf * 16][akoff]);
        aAddrL[mf] = smem_u32(&sA[1][arow + mf * 16][akoff]);
    }
    const int brow = nw * 32 + (lane >> 4) * 8 + (lane & 7);
    const int bkoff = ((lane >> 3) & 1) * 8;
    unsigned bAddrH[2], bAddrL[2];
#pragma unroll
    for (int p = 0; p < 2; p++) {
        bAddrH[p] = smem_u32(&sB[0][brow + p * 16][bkoff]);
        bAddrL[p] = smem_u32(&sB[1][brow + p * 16][bkoff]);
    }

    const int nchunks = K / GBK;
    for (int c = 0; c < nchunks; c++) {
        // Convert + store current chunk.
        split_store(&sA[0][grow][gcol],      &sA[1][grow][gcol],      a0v);
        split_store(&sA[0][grow + 64][gcol], &sA[1][grow + 64][gcol], a1v);
        split_store(&sB[0][grow][gcol],      &sB[1][grow][gcol],      b0v);
        split_store(&sB[0][grow + 64][gcol], &sB[1][grow + 64][gcol], b1v);
        __syncthreads();

        // Prefetch next chunk (overlapped with MMA phase).
        if (c + 1 < nchunks) {
            const int ko = (c + 1) * GBK;
            a0v = *(const float4*)(Ag + ko);
            a1v = *(const float4*)(Ag + (size_t)64 * K + ko);
            b0v = *(const float4*)(Bg + ko);
            b1v = *(const float4*)(Bg + (size_t)64 * K + ko);
        }

        // Load A fragments (hi + lo).
        unsigned ah[4][4], al[4][4];
#pragma unroll
        for (int mf = 0; mf < 4; mf++) {
            ldsm4(aAddrH[mf], ah[mf][0], ah[mf][1], ah[mf][2], ah[mf][3]);
            ldsm4(aAddrL[mf], al[mf][0], al[mf][1], al[mf][2], al[mf][3]);
        }

#pragma unroll
        for (int p = 0; p < 2; p++) {
            unsigned bh[4], bl[4];
            ldsm4(bAddrH[p], bh[0], bh[1], bh[2], bh[3]);
            ldsm4(bAddrL[p], bl[0], bl[1], bl[2], bl[3]);
#pragma unroll
            for (int mf = 0; mf < 4; mf++) {
                // hi*hi
                mma16816(acc[mf][2 * p],     ah[mf][0], ah[mf][1], ah[mf][2], ah[mf][3], bh[0], bh[1]);
                mma16816(acc[mf][2 * p + 1], ah[mf][0], ah[mf][1], ah[mf][2], ah[mf][3], bh[2], bh[3]);
                // hi*lo
                mma16816(acc[mf][2 * p],     ah[mf][0], ah[mf][1], ah[mf][2], ah[mf][3], bl[0], bl[1]);
                mma16816(acc[mf][2 * p + 1], ah[mf][0], ah[mf][1], ah[mf][2], ah[mf][3], bl[2], bl[3]);
                // lo*hi
                mma16816(acc[mf][2 * p],     al[mf][0], al[mf][1], al[mf][2], al[mf][3], bh[0], bh[1]);
                mma16816(acc[mf][2 * p + 1], al[mf][0], al[mf][1], al[mf][2], al[mf][3], bh[2], bh[3]);
            }
        }
        __syncthreads();
    }

    // Epilogue: bias add + fp32 store.
#pragma unroll
    for (int nf = 0; nf < 4; nf++) {
        int col = nw * 32 + nf * 8 + (lane & 3) * 2;
        float2 bb = *(const float2*)&bias[n0 + col];
#pragma unroll
        for (int mf = 0; mf < 4; mf++) {
            int row = m0 + mw * 64 + mf * 16 + (lane >> 2);
            float2 v0 = make_float2(acc[mf][nf][0] + bb.x, acc[mf][nf][1] + bb.y);
            *(float2*)&C[(size_t)row * N + n0 + col] = v0;
            float2 v1 = make_float2(acc[mf][nf][2] + bb.x, acc[mf][nf][3] + bb.y);
            *(float2*)&C[(size_t)(row + 8) * N + n0 + col] = v1;
        }
    }
}

// ---------------------------------------------------------------------------
// Flash-style attention (unchanged from R0): 1 CTA per (b, h, 64-row q tile).
// ---------------------------------------------------------------------------
#define ATT_PAD 2
#define ATT_STRIDE (64 + ATT_PAD)
#define ATTN_SMEM_FLOATS (3 * 64 * ATT_STRIDE + 8 * 8 * ATT_STRIDE + 64)
#define ATTN_SMEM_BYTES (ATTN_SMEM_FLOATS * 4)

__global__ __launch_bounds__(256) void attn_kernel(
    const float* __restrict__ Qp, const float* __restrict__ Kp,
    const float* __restrict__ Vp, const float* __restrict__ W,
    float* __restrict__ Ctx)
{
    extern __shared__ float sm[];
    float (*Qs)[ATT_STRIDE] = (float(*)[ATT_STRIDE])sm;
    float (*Ks)[ATT_STRIDE] = (float(*)[ATT_STRIDE])(sm + 64 * ATT_STRIDE);
    float (*Vs)[ATT_STRIDE] = (float(*)[ATT_STRIDE])(sm + 2 * 64 * ATT_STRIDE);
    float (*Ps)[8][ATT_STRIDE] = (float(*)[8][ATT_STRIDE])(sm + 3 * 64 * ATT_STRIDE);
    float* ws = sm + 3 * 64 * ATT_STRIDE + 8 * 8 * ATT_STRIDE;

    const int tid  = threadIdx.x;
    const int warp = tid >> 5;
    const int lane = tid & 31;
    const int qt = blockIdx.x, h = blockIdx.y, b = blockIdx.z;
    const int r0 = warp * 8;

    const float* qbase = Qp + ((size_t)(b * T_SEQ + qt * 64)) * E_DIM + h * D_K;
    for (int i = tid; i < 64 * 16; i += 256) {
        int r = i >> 4, c4 = (i & 15) << 2;
        float4 v = *(const float4*)(qbase + (size_t)r * E_DIM + c4);
        Qs[r][c4] = v.x; Qs[r][c4 + 1] = v.y; Qs[r][c4 + 2] = v.z; Qs[r][c4 + 3] = v.w;
    }

    float o0[8], o1[8], mrun[8], lrun[8];
#pragma unroll
    for (int r = 0; r < 8; r++) { o0[r] = 0.f; o1[r] = 0.f; mrun[r] = -1e30f; lrun[r] = 0.f; }

    for (int kt = 0; kt < T_SEQ / 64; kt++) {
        __syncthreads();
        const float* kbase = Kp + ((size_t)(b * T_SEQ + kt * 64)) * E_DIM + h * D_K;
        const float* vbase = Vp + ((size_t)(b * T_SEQ + kt * 64)) * E_DIM + h * D_K;
        for (int i = tid; i < 64 * 16; i += 256) {
            int r = i >> 4, c4 = (i & 15) << 2;
            float4 kv = *(const float4*)(kbase + (size_t)r * E_DIM + c4);
            Ks[r][c4] = kv.x; Ks[r][c4 + 1] = kv.y; Ks[r][c4 + 2] = kv.z; Ks[r][c4 + 3] = kv.w;
            float4 vv = *(const float4*)(vbase + (size_t)r * E_DIM + c4);
            Vs[r][c4] = vv.x; Vs[r][c4 + 1] = vv.y; Vs[r][c4 + 2] = vv.z; Vs[r][c4 + 3] = vv.w;
        }
        if (tid < 64) ws[tid] = W[b * T_SEQ + kt * 64 + tid];
        __syncthreads();

        float s0[8], s1[8];
#pragma unroll
        for (int r = 0; r < 8; r++) { s0[r] = 0.f; s1[r] = 0.f; }
#pragma unroll 4
        for (int d2 = 0; d2 < 32; d2++) {
            float2 k0 = *(const float2*)&Ks[lane][d2 * 2];
            float2 k1 = *(const float2*)&Ks[lane + 32][d2 * 2];
#pragma unroll
            for (int r = 0; r < 8; r++) {
                float2 q = *(const float2*)&Qs[r0 + r][d2 * 2];
                s0[r] += q.x * k0.x + q.y * k0.y;
                s1[r] += q.x * k1.x + q.y * k1.y;
            }
        }

        float w0 = ws[lane], w1 = ws[lane + 32];
        float f0 = SCALE * w0 * w0, f1 = SCALE * w1 * w1;
        bool msk0 = (w0 < WEPS), msk1 = (w1 < WEPS);
#pragma unroll
        for (int r = 0; r < 8; r++) {
            s0[r] = msk0 ? -1e30f : s0[r] * f0;
            s1[r] = msk1 ? -1e30f : s1[r] * f1;
        }

#pragma unroll
        for (int r = 0; r < 8; r++) {
            float mt = fmaxf(s0[r], s1[r]);
#pragma unroll
            for (int off = 16; off; off >>= 1)
                mt = fmaxf(mt, __shfl_xor_sync(0xffffffffu, mt, off));
            float mnew = fmaxf(mrun[r], mt);
            float p0 = (s0[r] < -1e29f) ? 0.f : __expf(s0[r] - mnew);
            float p1 = (s1[r] < -1e29f) ? 0.f : __expf(s1[r] - mnew);
            float alpha = __expf(mrun[r] - mnew);
            float pt = p0 + p1;
#pragma unroll
            for (int off = 16; off; off >>= 1)
                pt += __shfl_xor_sync(0xffffffffu, pt, off);
            lrun[r] = lrun[r] * alpha + pt;
            o0[r] *= alpha;
            o1[r] *= alpha;
            mrun[r] = mnew;
            Ps[warp][r][lane] = p0;
            Ps[warp][r][lane + 32] = p1;
        }
        __syncwarp();

#pragma unroll 4
        for (int c2 = 0; c2 < 32; c2++) {
            int c = c2 * 2;
            float v00 = Vs[c][lane],     v01 = Vs[c][lane + 32];
            float v10 = Vs[c + 1][lane], v11 = Vs[c + 1][lane + 32];
#pragma unroll
            for (int r = 0; r < 8; r++) {
                float2 p = *(const float2*)&Ps[warp][r][c];
                o0[r] += p.x * v00 + p.y * v10;
                o1[r] += p.x * v01 + p.y * v11;
            }
        }
    }

    float* obase = Ctx + ((size_t)(b * T_SEQ + qt * 64 + r0)) * E_DIM + h * D_K;
#pragma unroll
    for (int r = 0; r < 8; r++) {
        float inv = 1.f / lrun[r];
        obase[(size_t)r * E_DIM + lane]      = o0[r] * inv;
        obase[(size_t)r * E_DIM + lane + 32] = o1[r] * inv;
    }
}

// ---------------------------------------------------------------------------
extern "C" void kernel_launch(void* const* d_in, const int* in_sizes, int n_in,
                              void* d_out, int out_size)
{
    const float* q  = (const float*)d_in[0];
    const float* k  = (const float*)d_in[1];
    const float* v  = (const float*)d_in[2];
    const float* wt = (const float*)d_in[3];
    const float* Wq = (const float*)d_in[4];
    const float* bq = (const float*)d_in[5];
    const float* Wk = (const float*)d_in[6];
    const float* bk = (const float*)d_in[7];
    const float* Wv = (const float*)d_in[8];
    const float* bv = (const float*)d_in[9];
    const float* Wo = (const float*)d_in[10];
    const float* bo = (const float*)d_in[11];

    float *Qp, *Kp, *Vp, *Ctx;
    cudaGetSymbolAddress((void**)&Qp, g_Qp);
    cudaGetSymbolAddress((void**)&Kp, g_Kp);
    cudaGetSymbolAddress((void**)&Vp, g_Vp);
    cudaGetSymbolAddress((void**)&Ctx, g_Ctx);

    cudaFuncSetAttribute(attn_kernel, cudaFuncAttributeMaxDynamicSharedMemorySize,
                         ATTN_SMEM_BYTES);

    const int M = BATCH * T_SEQ;   // 4096
    const int N = E_DIM, K = E_DIM;
    dim3 gg(N / GBN, M / GBM);     // (8, 32)

    gemm_nt_bias_tc<<<gg, 256>>>(q, Wq, bq, Qp, M, N, K);
    gemm_nt_bias_tc<<<gg, 256>>>(k, Wk, bk, Kp, M, N, K);
    gemm_nt_bias_tc<<<gg, 256>>>(v, Wv, bv, Vp, M, N, K);

    dim3 ga(T_SEQ / 64, N_HEAD, BATCH);  // (16, 16, 4)
    attn_kernel<<<ga, 256, ATTN_SMEM_BYTES>>>(Qp, Kp, Vp, wt, Ctx);

    gemm_nt_bias_tc<<<gg, 256>>>(Ctx, Wo, bo, (float*)d_out, M, N, K);
}

// round 3
// speedup vs baseline: 2.3133x; 1.5729x over previous
#include <cuda_runtime.h>
#include <cuda_bf16.h>
#include <cstddef>

#define E_DIM 1024
#define T_SEQ 1024
#define BATCH 4
#define N_HEAD 16
#define SCALE 0.125f
#define WEPS 1e-5f

// Scratch (allocation-free rule: __device__ globals)
__device__ __nv_bfloat16 g_Qhi[BATCH * T_SEQ * E_DIM];
__device__ __nv_bfloat16 g_Qlo[BATCH * T_SEQ * E_DIM];
__device__ __nv_bfloat16 g_Khi[BATCH * T_SEQ * E_DIM];
__device__ __nv_bfloat16 g_Klo[BATCH * T_SEQ * E_DIM];
__device__ __nv_bfloat16 g_Vhi[BATCH * T_SEQ * E_DIM];
__device__ __nv_bfloat16 g_Vlo[BATCH * T_SEQ * E_DIM];
__device__ float g_Ctx[BATCH * T_SEQ * E_DIM];

// ---------------------------------------------------------------------------
// PTX helpers
// ---------------------------------------------------------------------------
__device__ __forceinline__ unsigned smem_u32(const void* p) {
    return (unsigned)__cvta_generic_to_shared(p);
}
__device__ __forceinline__ void ldsm4(unsigned addr, unsigned& r0, unsigned& r1,
                                      unsigned& r2, unsigned& r3) {
    asm volatile("ldmatrix.sync.aligned.m8n8.x4.shared.b16 {%0,%1,%2,%3}, [%4];"
                 : "=r"(r0), "=r"(r1), "=r"(r2), "=r"(r3) : "r"(addr));
}
__device__ __forceinline__ void ldsm4t(unsigned addr, unsigned& r0, unsigned& r1,
                                       unsigned& r2, unsigned& r3) {
    asm volatile("ldmatrix.sync.aligned.m8n8.x4.trans.shared.b16 {%0,%1,%2,%3}, [%4];"
                 : "=r"(r0), "=r"(r1), "=r"(r2), "=r"(r3) : "r"(addr));
}
__device__ __forceinline__ void mma16816(float* c, unsigned a0, unsigned a1,
                                         unsigned a2, unsigned a3,
                                         unsigned b0, unsigned b1) {
    asm volatile(
        "mma.sync.aligned.m16n8k16.row.col.f32.bf16.bf16.f32 "
        "{%0,%1,%2,%3},{%4,%5,%6,%7},{%8,%9},{%0,%1,%2,%3};"
        : "+f"(c[0]), "+f"(c[1]), "+f"(c[2]), "+f"(c[3])
        : "r"(a0), "r"(a1), "r"(a2), "r"(a3), "r"(b0), "r"(b1));
}

// split fp32 -> bf16 hi + bf16 lo
__device__ __forceinline__ void split_store(__nv_bfloat16* hi, __nv_bfloat16* lo,
                                            float4 v) {
    __nv_bfloat16 h;
    h = __float2bfloat16_rn(v.x); hi[0] = h; lo[0] = __float2bfloat16_rn(v.x - __bfloat162float(h));
    h = __float2bfloat16_rn(v.y); hi[1] = h; lo[1] = __float2bfloat16_rn(v.y - __bfloat162float(h));
    h = __float2bfloat16_rn(v.z); hi[2] = h; lo[2] = __float2bfloat16_rn(v.z - __bfloat162float(h));
    h = __float2bfloat16_rn(v.w); hi[3] = h; lo[3] = __float2bfloat16_rn(v.w - __bfloat162float(h));
}

// split two floats into packed bf16x2 hi + lo
__device__ __forceinline__ void split2(float x, float y, unsigned& hi, unsigned& lo) {
    __nv_bfloat162 h = __floats2bfloat162_rn(x, y);
    float hx = __bfloat162float(h.x), hy = __bfloat162float(h.y);
    __nv_bfloat162 l = __floats2bfloat162_rn(x - hx, y - hy);
    hi = *(unsigned*)&h;
    lo = *(unsigned*)&l;
}

// ---------------------------------------------------------------------------
// Tensor-core GEMM (bf16-split): C = A[M,K] @ B[N,K]^T + bias[N]
// SPLIT=true: write hi/lo bf16 buffers; else fp32.
// ---------------------------------------------------------------------------
#define GBM 128
#define GBN 128
#define GBK 16
#define GST 24

template<bool SPLIT>
__global__ __launch_bounds__(256) void gemm_nt_bias_tc(
    const float* __restrict__ A, const float* __restrict__ B,
    const float* __restrict__ bias, float* __restrict__ Cf,
    __nv_bfloat16* __restrict__ Chi, __nv_bfloat16* __restrict__ Clo,
    int M, int N, int K)
{
    __shared__ __nv_bfloat16 sA[2][GBM][GST];
    __shared__ __nv_bfloat16 sB[2][GBN][GST];

    const int tid = threadIdx.x;
    const int lane = tid & 31;
    const int warp = tid >> 5;
    const int mw = warp >> 2;
    const int nw = warp & 3;
    const int m0 = blockIdx.y * GBM;
    const int n0 = blockIdx.x * GBN;

    const int grow = tid >> 2;
    const int gcol = (tid & 3) * 4;
    const float* Ag = A + (size_t)(m0 + grow) * K + gcol;
    const float* Bg = B + (size_t)(n0 + grow) * K + gcol;

    float4 a0v = *(const float4*)(Ag);
    float4 a1v = *(const float4*)(Ag + (size_t)64 * K);
    float4 b0v = *(const float4*)(Bg);
    float4 b1v = *(const float4*)(Bg + (size_t)64 * K);

    float acc[4][4][4];
#pragma unroll
    for (int i = 0; i < 4; i++)
#pragma unroll
        for (int j = 0; j < 4; j++)
#pragma unroll
            for (int l = 0; l < 4; l++) acc[i][j][l] = 0.f;

    const int arow = mw * 64 + (lane & 15);
    const int akoff = (lane >> 4) * 8;
    unsigned aAddrH[4], aAddrL[4];
#pragma unroll
    for (int mf = 0; mf < 4; mf++) {
        aAddrH[mf] = smem_u32(&sA[0][arow + mf * 16][akoff]);
        aAddrL[mf] = smem_u32(&sA[1][arow + mf * 16][akoff]);
    }
    const int brow = nw * 32 + (lane >> 4) * 8 + (lane & 7);
    const int bkoff = ((lane >> 3) & 1) * 8;
    unsigned bAddrH[2], bAddrL[2];
#pragma unroll
    for (int p = 0; p < 2; p++) {
        bAddrH[p] = smem_u32(&sB[0][brow + p * 16][bkoff]);
        bAddrL[p] = smem_u32(&sB[1][brow + p * 16][bkoff]);
    }

    const int nchunks = K / GBK;
    for (int c = 0; c < nchunks; c++) {
        split_store(&sA[0][grow][gcol],      &sA[1][grow][gcol],      a0v);
        split_store(&sA[0][grow + 64][gcol], &sA[1][grow + 64][gcol], a1v);
        split_store(&sB[0][grow][gcol],      &sB[1][grow][gcol],      b0v);
        split_store(&sB[0][grow + 64][gcol], &sB[1][grow + 64][gcol], b1v);
        __syncthreads();

        if (c + 1 < nchunks) {
            const int ko = (c + 1) * GBK;
            a0v = *(const float4*)(Ag + ko);
            a1v = *(const float4*)(Ag + (size_t)64 * K + ko);
            b0v = *(const float4*)(Bg + ko);
            b1v = *(const float4*)(Bg + (size_t)64 * K + ko);
        }

        unsigned ah[4][4], al[4][4];
#pragma unroll
        for (int mf = 0; mf < 4; mf++) {
            ldsm4(aAddrH[mf], ah[mf][0], ah[mf][1], ah[mf][2], ah[mf][3]);
            ldsm4(aAddrL[mf], al[mf][0], al[mf][1], al[mf][2], al[mf][3]);
        }

#pragma unroll
        for (int p = 0; p < 2; p++) {
            unsigned bh[4], bl[4];
            ldsm4(bAddrH[p], bh[0], bh[1], bh[2], bh[3]);
            ldsm4(bAddrL[p], bl[0], bl[1], bl[2], bl[3]);
#pragma unroll
            for (int mf = 0; mf < 4; mf++) {
                mma16816(acc[mf][2 * p],     ah[mf][0], ah[mf][1], ah[mf][2], ah[mf][3], bh[0], bh[1]);
                mma16816(acc[mf][2 * p + 1], ah[mf][0], ah[mf][1], ah[mf][2], ah[mf][3], bh[2], bh[3]);
                mma16816(acc[mf][2 * p],     ah[mf][0], ah[mf][1], ah[mf][2], ah[mf][3], bl[0], bl[1]);
                mma16816(acc[mf][2 * p + 1], ah[mf][0], ah[mf][1], ah[mf][2], ah[mf][3], bl[2], bl[3]);
                mma16816(acc[mf][2 * p],     al[mf][0], al[mf][1], al[mf][2], al[mf][3], bh[0], bh[1]);
                mma16816(acc[mf][2 * p + 1], al[mf][0], al[mf][1], al[mf][2], al[mf][3], bh[2], bh[3]);
            }
        }
        __syncthreads();
    }

#pragma unroll
    for (int nf = 0; nf < 4; nf++) {
        int col = nw * 32 + nf * 8 + (lane & 3) * 2;
        float2 bb = *(const float2*)&bias[n0 + col];
#pragma unroll
        for (int mf = 0; mf < 4; mf++) {
            int row = m0 + mw * 64 + mf * 16 + (lane >> 2);
            float x0 = acc[mf][nf][0] + bb.x, y0 = acc[mf][nf][1] + bb.y;
            float x1 = acc[mf][nf][2] + bb.x, y1 = acc[mf][nf][3] + bb.y;
            if (SPLIT) {
                unsigned h0, l0, h1, l1;
                split2(x0, y0, h0, l0);
                split2(x1, y1, h1, l1);
                *(unsigned*)&Chi[(size_t)row * N + n0 + col] = h0;
                *(unsigned*)&Clo[(size_t)row * N + n0 + col] = l0;
                *(unsigned*)&Chi[(size_t)(row + 8) * N + n0 + col] = h1;
                *(unsigned*)&Clo[(size_t)(row + 8) * N + n0 + col] = l1;
            } else {
                *(float2*)&Cf[(size_t)row * N + n0 + col] = make_float2(x0, y0);
                *(float2*)&Cf[(size_t)(row + 8) * N + n0 + col] = make_float2(x1, y1);
            }
        }
    }
}

// ---------------------------------------------------------------------------
// Tensor-core flash attention. CTA: 128 q-rows x (b,h); 8 warps x 16 rows.
// Key tiles of 64. S and O via bf16-split MMA; softmax on C-fragments.
// ---------------------------------------------------------------------------
#define AST 72   // bf16 row stride (144B)
// smem: Qh/Ql 128x72, Kh/Kl 64x72, Vh/Vl 64x72 (bf16) + ws[64] (f32)
#define ATTN_SMEM_BYTES (36864 * 2 + 256)

__global__ __launch_bounds__(256) void attn_tc(
    const __nv_bfloat16* __restrict__ Qhi, const __nv_bfloat16* __restrict__ Qlo,
    const __nv_bfloat16* __restrict__ Khi, const __nv_bfloat16* __restrict__ Klo,
    const __nv_bfloat16* __restrict__ Vhi, const __nv_bfloat16* __restrict__ Vlo,
    const float* __restrict__ W, float* __restrict__ Ctx)
{
    extern __shared__ char smc[];
    __nv_bfloat16 (*sQh)[AST] = (__nv_bfloat16(*)[AST])(smc);
    __nv_bfloat16 (*sQl)[AST] = (__nv_bfloat16(*)[AST])(smc + 18432);
    __nv_bfloat16 (*sKh)[AST] = (__nv_bfloat16(*)[AST])(smc + 36864);
    __nv_bfloat16 (*sKl)[AST] = (__nv_bfloat16(*)[AST])(smc + 46080);
    __nv_bfloat16 (*sVh)[AST] = (__nv_bfloat16(*)[AST])(smc + 55296);
    __nv_bfloat16 (*sVl)[AST] = (__nv_bfloat16(*)[AST])(smc + 64512);
    float* ws = (float*)(smc + 73728);

    const int tid = threadIdx.x, lane = tid & 31, warp = tid >> 5;
    const int qt = blockIdx.x, h = blockIdx.y, b = blockIdx.z;

    // Load Q tile (128 x 64 hi/lo)
    const size_t qg = ((size_t)(b * T_SEQ + qt * 128)) * E_DIM + h * 64;
#pragma unroll
    for (int it = 0; it < 4; it++) {
        int i = tid + it * 256;
        int r = i >> 3, c = (i & 7) * 8;
        *(uint4*)&sQh[r][c] = *(const uint4*)&Qhi[qg + (size_t)r * E_DIM + c];
        *(uint4*)&sQl[r][c] = *(const uint4*)&Qlo[qg + (size_t)r * E_DIM + c];
    }

    // Fragment addresses
    const int arow = warp * 16 + (lane & 15);
    const int akoff = (lane >> 4) * 8;
    const unsigned aH = smem_u32(&sQh[arow][akoff]);
    const unsigned aL = smem_u32(&sQl[arow][akoff]);
    const int brow = (lane >> 4) * 8 + (lane & 7);
    const int bkoff = ((lane >> 3) & 1) * 8;
    const unsigned kH = smem_u32(&sKh[brow][bkoff]);
    const unsigned kL = smem_u32(&sKl[brow][bkoff]);
    const int vr = (lane & 7) + ((lane >> 3) & 1) * 8;
    const int vc = (lane >> 4) * 8;
    const unsigned vH = smem_u32(&sVh[vr][vc]);
    const unsigned vL = smem_u32(&sVl[vr][vc]);

    float o[8][4];
#pragma unroll
    for (int nf = 0; nf < 8; nf++)
#pragma unroll
        for (int j = 0; j < 4; j++) o[nf][j] = 0.f;
    float mA = -1e30f, mB = -1e30f, lA = 0.f, lB = 0.f;

    for (int kt = 0; kt < T_SEQ / 64; kt++) {
        __syncthreads();
        const size_t kg = ((size_t)(b * T_SEQ + kt * 64)) * E_DIM + h * 64;
#pragma unroll
        for (int it = 0; it < 2; it++) {
            int i = tid + it * 256;
            int r = i >> 3, c = (i & 7) * 8;
            size_t off = kg + (size_t)r * E_DIM + c;
            *(uint4*)&sKh[r][c] = *(const uint4*)&Khi[off];
            *(uint4*)&sKl[r][c] = *(const uint4*)&Klo[off];
            *(uint4*)&sVh[r][c] = *(const uint4*)&Vhi[off];
            *(uint4*)&sVl[r][c] = *(const uint4*)&Vlo[off];
        }
        if (tid < 64) ws[tid] = W[b * T_SEQ + kt * 64 + tid];
        __syncthreads();

        // ---- S = Q K^T (bf16-split) ----
        float s[8][4];
#pragma unroll
        for (int nf = 0; nf < 8; nf++)
#pragma unroll
            for (int j = 0; j < 4; j++) s[nf][j] = 0.f;

#pragma unroll
        for (int kc = 0; kc < 4; kc++) {
            unsigned ah[4], al[4];
            ldsm4(aH + kc * 32, ah[0], ah[1], ah[2], ah[3]);
            ldsm4(aL + kc * 32, al[0], al[1], al[2], al[3]);
#pragma unroll
            for (int g = 0; g < 4; g++) {
                unsigned bh[4], bl[4];
                ldsm4(kH + g * 2304 + kc * 32, bh[0], bh[1], bh[2], bh[3]);
                ldsm4(kL + g * 2304 + kc * 32, bl[0], bl[1], bl[2], bl[3]);
                mma16816(s[2 * g],     ah[0], ah[1], ah[2], ah[3], bh[0], bh[1]);
                mma16816(s[2 * g + 1], ah[0], ah[1], ah[2], ah[3], bh[2], bh[3]);
                mma16816(s[2 * g],     ah[0], ah[1], ah[2], ah[3], bl[0], bl[1]);
                mma16816(s[2 * g + 1], ah[0], ah[1], ah[2], ah[3], bl[2], bl[3]);
                mma16816(s[2 * g],     al[0], al[1], al[2], al[3], bh[0], bh[1]);
                mma16816(s[2 * g + 1], al[0], al[1], al[2], al[3], bh[2], bh[3]);
            }
        }

        // ---- scale + weight mask ----
#pragma unroll
        for (int nf = 0; nf < 8; nf++) {
            float2 wp = *(const float2*)&ws[nf * 8 + (lane & 3) * 2];
            float f0 = SCALE * wp.x * wp.x, f1 = SCALE * wp.y * wp.y;
            s[nf][0] = (wp.x < WEPS) ? -1e30f : s[nf][0] * f0;
            s[nf][1] = (wp.y < WEPS) ? -1e30f : s[nf][1] * f1;
            s[nf][2] = (wp.x < WEPS) ? -1e30f : s[nf][2] * f0;
            s[nf][3] = (wp.y < WEPS) ? -1e30f : s[nf][3] * f1;
        }

        // ---- online softmax (rows: A = lane/4, B = lane/4+8) ----
        float tmA = -1e30f, tmB = -1e30f;
#pragma unroll
        for (int nf = 0; nf < 8; nf++) {
            tmA = fmaxf(tmA, fmaxf(s[nf][0], s[nf][1]));
            tmB = fmaxf(tmB, fmaxf(s[nf][2], s[nf][3]));
        }
        tmA = fmaxf(tmA, __shfl_xor_sync(0xffffffffu, tmA, 1));
        tmA = fmaxf(tmA, __shfl_xor_sync(0xffffffffu, tmA, 2));
        tmB = fmaxf(tmB, __shfl_xor_sync(0xffffffffu, tmB, 1));
        tmB = fmaxf(tmB, __shfl_xor_sync(0xffffffffu, tmB, 2));
        float mnA = fmaxf(mA, tmA), mnB = fmaxf(mB, tmB);
        float alA = __expf(mA - mnA), alB = __expf(mB - mnB);

        float sumA = 0.f, sumB = 0.f;
#pragma unroll
        for (int nf = 0; nf < 8; nf++) {
            s[nf][0] = (s[nf][0] < -1e29f) ? 0.f : __expf(s[nf][0] - mnA);
            s[nf][1] = (s[nf][1] < -1e29f) ? 0.f : __expf(s[nf][1] - mnA);
            s[nf][2] = (s[nf][2] < -1e29f) ? 0.f : __expf(s[nf][2] - mnB);
            s[nf][3] = (s[nf][3] < -1e29f) ? 0.f : __expf(s[nf][3] - mnB);
            sumA += s[nf][0] + s[nf][1];
            sumB += s[nf][2] + s[nf][3];
        }
        sumA += __shfl_xor_sync(0xffffffffu, sumA, 1);
        sumA += __shfl_xor_sync(0xffffffffu, sumA, 2);
        sumB += __shfl_xor_sync(0xffffffffu, sumB, 1);
        sumB += __shfl_xor_sync(0xffffffffu, sumB, 2);
        lA = lA * alA + sumA;
        lB = lB * alB + sumB;
        mA = mnA; mB = mnB;
#pragma unroll
        for (int nf = 0; nf < 8; nf++) {
            o[nf][0] *= alA; o[nf][1] *= alA;
            o[nf][2] *= alB; o[nf][3] *= alB;
        }

        // ---- repack P into A-fragments (hi/lo) ----
        unsigned ph[4][4], pl[4][4];
#pragma unroll
        for (int kc = 0; kc < 4; kc++) {
            split2(s[2 * kc][0],     s[2 * kc][1],     ph[kc][0], pl[kc][0]);
            split2(s[2 * kc][2],     s[2 * kc][3],     ph[kc][1], pl[kc][1]);
            split2(s[2 * kc + 1][0], s[2 * kc + 1][1], ph[kc][2], pl[kc][2]);
            split2(s[2 * kc + 1][2], s[2 * kc + 1][3], ph[kc][3], pl[kc][3]);
        }

        // ---- O += P V (bf16-split), V via ldmatrix.trans ----
#pragma unroll
        for (int p = 0; p < 4; p++) {
#pragma unroll
            for (int kc = 0; kc < 4; kc++) {
                unsigned vh[4], vl[4];
                ldsm4t(vH + kc * 2304 + p * 32, vh[0], vh[1], vh[2], vh[3]);
                ldsm4t(vL + kc * 2304 + p * 32, vl[0], vl[1], vl[2], vl[3]);
                mma16816(o[2 * p],     ph[kc][0], ph[kc][1], ph[kc][2], ph[kc][3], vh[0], vh[1]);
                mma16816(o[2 * p + 1], ph[kc][0], ph[kc][1], ph[kc][2], ph[kc][3], vh[2], vh[3]);
                mma16816(o[2 * p],     ph[kc][0], ph[kc][1], ph[kc][2], ph[kc][3], vl[0], vl[1]);
                mma16816(o[2 * p + 1], ph[kc][0], ph[kc][1], ph[kc][2], ph[kc][3], vl[2], vl[3]);
                mma16816(o[2 * p],     pl[kc][0], pl[kc][1], pl[kc][2], pl[kc][3], vh[0], vh[1]);
                mma16816(o[2 * p + 1], pl[kc][0], pl[kc][1], pl[kc][2], pl[kc][3], vh[2], vh[3]);
            }
        }
    }

    // ---- epilogue ----
    const int rA = qt * 128 + warp * 16 + (lane >> 2);
    const float invA = 1.f / lA, invB = 1.f / lB;
    const size_t ob = ((size_t)(b * T_SEQ)) * E_DIM + h * 64;
#pragma unroll
    for (int nf = 0; nf < 8; nf++) {
        int col = nf * 8 + (lane & 3) * 2;
        *(float2*)&Ctx[ob + (size_t)rA * E_DIM + col] =
            make_float2(o[nf][0] * invA, o[nf][1] * invA);
        *(float2*)&Ctx[ob + (size_t)(rA + 8) * E_DIM + col] =
            make_float2(o[nf][2] * invB, o[nf][3] * invB);
    }
}

// ---------------------------------------------------------------------------
extern "C" void kernel_launch(void* const* d_in, const int* in_sizes, int n_in,
                              void* d_out, int out_size)
{
    const float* q  = (const float*)d_in[0];
    const float* k  = (const float*)d_in[1];
    const float* v  = (const float*)d_in[2];
    const float* wt = (const float*)d_in[3];
    const float* Wq = (const float*)d_in[4];
    const float* bq = (const float*)d_in[5];
    const float* Wk = (const float*)d_in[6];
    const float* bk = (const float*)d_in[7];
    const float* Wv = (const float*)d_in[8];
    const float* bv = (const float*)d_in[9];
    const float* Wo = (const float*)d_in[10];
    const float* bo = (const float*)d_in[11];

    __nv_bfloat16 *Qh, *Ql, *Kh, *Kl, *Vh, *Vl;
    float* Ctx;
    cudaGetSymbolAddress((void**)&Qh, g_Qhi);
    cudaGetSymbolAddress((void**)&Ql, g_Qlo);
    cudaGetSymbolAddress((void**)&Kh, g_Khi);
    cudaGetSymbolAddress((void**)&Kl, g_Klo);
    cudaGetSymbolAddress((void**)&Vh, g_Vhi);
    cudaGetSymbolAddress((void**)&Vl, g_Vlo);
    cudaGetSymbolAddress((void**)&Ctx, g_Ctx);

    cudaFuncSetAttribute(attn_tc, cudaFuncAttributeMaxDynamicSharedMemorySize,
                         ATTN_SMEM_BYTES);

    const int M = BATCH * T_SEQ;
    const int N = E_DIM, K = E_DIM;
    dim3 gg(N / GBN, M / GBM);

    gemm_nt_bias_tc<true><<<gg, 256>>>(q, Wq, bq, nullptr, Qh, Ql, M, N, K);
    gemm_nt_bias_tc<true><<<gg, 256>>>(k, Wk, bk, nullptr, Kh, Kl, M, N, K);
    gemm_nt_bias_tc<true><<<gg, 256>>>(v, Wv, bv, nullptr, Vh, Vl, M, N, K);

    dim3 ga(T_SEQ / 128, N_HEAD, BATCH);  // (8, 16, 4)
    attn_tc<<<ga, 256, ATTN_SMEM_BYTES>>>(Qh, Ql, Kh, Kl, Vh, Vl, wt, Ctx);

    gemm_nt_bias_tc<false><<<gg, 256>>>(Ctx, Wo, bo, (float*)d_out, nullptr, nullptr, M, N, K);
}

// round 4
// speedup vs baseline: 2.6432x; 1.1426x over previous
#include <cuda_runtime.h>
#include <cuda_bf16.h>
#include <cstddef>

#define E_DIM 1024
#define T_SEQ 1024
#define BATCH 4
#define N_HEAD 16
#define SCALE 0.125f
#define WEPS 1e-5f

// Scratch (allocation-free rule: __device__ globals)
__device__ __nv_bfloat16 g_Qhi[BATCH * T_SEQ * E_DIM];
__device__ __nv_bfloat16 g_Qlo[BATCH * T_SEQ * E_DIM];
__device__ __nv_bfloat16 g_Khi[BATCH * T_SEQ * E_DIM];
__device__ __nv_bfloat16 g_Klo[BATCH * T_SEQ * E_DIM];
__device__ __nv_bfloat16 g_Vhi[BATCH * T_SEQ * E_DIM];
__device__ __nv_bfloat16 g_Vlo[BATCH * T_SEQ * E_DIM];
__device__ __nv_bfloat16 g_Chi[BATCH * T_SEQ * E_DIM];   // attention ctx (split)
__device__ __nv_bfloat16 g_Clo[BATCH * T_SEQ * E_DIM];
// split inputs / weights
__device__ __nv_bfloat16 g_qhi[BATCH * T_SEQ * E_DIM];
__device__ __nv_bfloat16 g_qlo[BATCH * T_SEQ * E_DIM];
__device__ __nv_bfloat16 g_khi[BATCH * T_SEQ * E_DIM];
__device__ __nv_bfloat16 g_klo[BATCH * T_SEQ * E_DIM];
__device__ __nv_bfloat16 g_vhi[BATCH * T_SEQ * E_DIM];
__device__ __nv_bfloat16 g_vlo[BATCH * T_SEQ * E_DIM];
__device__ __nv_bfloat16 g_Wqh[E_DIM * E_DIM], g_Wql[E_DIM * E_DIM];
__device__ __nv_bfloat16 g_Wkh[E_DIM * E_DIM], g_Wkl[E_DIM * E_DIM];
__device__ __nv_bfloat16 g_Wvh[E_DIM * E_DIM], g_Wvl[E_DIM * E_DIM];
__device__ __nv_bfloat16 g_Woh[E_DIM * E_DIM], g_Wol[E_DIM * E_DIM];

// ---------------------------------------------------------------------------
// PTX helpers
// ---------------------------------------------------------------------------
__device__ __forceinline__ unsigned smem_u32(const void* p) {
    return (unsigned)__cvta_generic_to_shared(p);
}
__device__ __forceinline__ void ldsm4(unsigned addr, unsigned& r0, unsigned& r1,
                                      unsigned& r2, unsigned& r3) {
    asm volatile("ldmatrix.sync.aligned.m8n8.x4.shared.b16 {%0,%1,%2,%3}, [%4];"
                 : "=r"(r0), "=r"(r1), "=r"(r2), "=r"(r3) : "r"(addr));
}
__device__ __forceinline__ void ldsm4t(unsigned addr, unsigned& r0, unsigned& r1,
                                       unsigned& r2, unsigned& r3) {
    asm volatile("ldmatrix.sync.aligned.m8n8.x4.trans.shared.b16 {%0,%1,%2,%3}, [%4];"
                 : "=r"(r0), "=r"(r1), "=r"(r2), "=r"(r3) : "r"(addr));
}
__device__ __forceinline__ void mma16816(float* c, unsigned a0, unsigned a1,
                                         unsigned a2, unsigned a3,
                                         unsigned b0, unsigned b1) {
    asm volatile(
        "mma.sync.aligned.m16n8k16.row.col.f32.bf16.bf16.f32 "
        "{%0,%1,%2,%3},{%4,%5,%6,%7},{%8,%9},{%0,%1,%2,%3};"
        : "+f"(c[0]), "+f"(c[1]), "+f"(c[2]), "+f"(c[3])
        : "r"(a0), "r"(a1), "r"(a2), "r"(a3), "r"(b0), "r"(b1));
}
__device__ __forceinline__ void cp16(unsigned dst, const void* src) {
    asm volatile("cp.async.cg.shared.global [%0], [%1], 16;" :: "r"(dst), "l"(src));
}

// split two floats into packed bf16x2 hi + lo
__device__ __forceinline__ void split2(float x, float y, unsigned& hi, unsigned& lo) {
    __nv_bfloat162 h = __floats2bfloat162_rn(x, y);
    float hx = __bfloat162float(h.x), hy = __bfloat162float(h.y);
    __nv_bfloat162 l = __floats2bfloat162_rn(x - hx, y - hy);
    hi = *(unsigned*)&h;
    lo = *(unsigned*)&l;
}

// ---------------------------------------------------------------------------
// fp32 -> split bf16 hi/lo converter (bandwidth-bound pre-pass)
// ---------------------------------------------------------------------------
__global__ __launch_bounds__(256) void split_kernel(
    const float* __restrict__ x, __nv_bfloat16* __restrict__ hi,
    __nv_bfloat16* __restrict__ lo, int n)
{
    int i = (blockIdx.x * 256 + threadIdx.x) * 4;
    if (i >= n) return;
    float4 v = *(const float4*)(x + i);
    unsigned h0, l0, h1, l1;
    split2(v.x, v.y, h0, l0);
    split2(v.z, v.w, h1, l1);
    uint2 hh = make_uint2(h0, h1), ll = make_uint2(l0, l1);
    *(uint2*)(hi + i) = hh;
    *(uint2*)(lo + i) = ll;
}

// ---------------------------------------------------------------------------
// bf16-split GEMM, pre-split inputs: C = A[M,K] @ B[N,K]^T + bias[N]
// BM=128, BN=128, BK=16, 256 threads, double-buffered cp.async, occ 2.
// ---------------------------------------------------------------------------
#define GST 24
#define SA_HL 6144        // bytes per hi/lo plane: 128*24*2
#define SA_STAGE 12288    // bytes per stage (hi+lo)
#define SB_OFF 24576      // sB base offset
#define GEMM_SMEM 49152

template<bool SPLIT_OUT>
__global__ __launch_bounds__(256, 2) void gemm_splitin(
    const __nv_bfloat16* __restrict__ Ahi, const __nv_bfloat16* __restrict__ Alo,
    const __nv_bfloat16* __restrict__ Bhi, const __nv_bfloat16* __restrict__ Blo,
    const float* __restrict__ bias, float* __restrict__ Cf,
    __nv_bfloat16* __restrict__ Chi, __nv_bfloat16* __restrict__ Clo,
    int M, int N, int K)
{
    extern __shared__ char smraw[];

    const int tid = threadIdx.x;
    const int lane = tid & 31;
    const int warp = tid >> 5;
    const int mw = warp >> 2;
    const int nw = warp & 3;
    const int m0 = blockIdx.y * 128;
    const int n0 = blockIdx.x * 128;

    // cp.async mapping: thread -> row tid>>1 (0..127), 16B chunk (tid&1)
    const int grow = tid >> 1;
    const int gc8 = (tid & 1) * 8;
    const size_t aoff = (size_t)(m0 + grow) * K + gc8;
    const size_t boff = (size_t)(n0 + grow) * K + gc8;
    const unsigned sArow = smem_u32(smraw) + grow * (GST * 2) + gc8 * 2;
    const unsigned sBrow = smem_u32(smraw) + SB_OFF + grow * (GST * 2) + gc8 * 2;

    float acc[4][4][4];
#pragma unroll
    for (int i = 0; i < 4; i++)
#pragma unroll
        for (int j = 0; j < 4; j++)
#pragma unroll
            for (int l = 0; l < 4; l++) acc[i][j][l] = 0.f;

    // fragment base addresses (stage 0)
    const int arow = mw * 64 + (lane & 15);
    const int akoff = (lane >> 4) * 8;
    const unsigned aH0 = smem_u32(smraw) + arow * (GST * 2) + akoff * 2;
    const int brow = nw * 32 + (lane >> 4) * 8 + (lane & 7);
    const int bkoff = ((lane >> 3) & 1) * 8;
    const unsigned bH0 = smem_u32(smraw) + SB_OFF + brow * (GST * 2) + bkoff * 2;

    // prologue: stage 0
    cp16(sArow, Ahi + aoff);
    cp16(sArow + SA_HL, Alo + aoff);
    cp16(sBrow, Bhi + boff);
    cp16(sBrow + SA_HL, Blo + boff);
    asm volatile("cp.async.commit_group;");

    const int nchunks = K / 16;
    for (int c = 0; c < nchunks; c++) {
        if (c + 1 < nchunks) {
            const int st = (c + 1) & 1;
            const int ko = (c + 1) * 16;
            cp16(sArow + st * SA_STAGE, Ahi + aoff + ko);
            cp16(sArow + st * SA_STAGE + SA_HL, Alo + aoff + ko);
            cp16(sBrow + st * SA_STAGE, Bhi + boff + ko);
            cp16(sBrow + st * SA_STAGE + SA_HL, Blo + boff + ko);
            asm volatile("cp.async.commit_group;");
            asm volatile("cp.async.wait_group 1;");
        } else {
            asm volatile("cp.async.wait_group 0;");
        }
        __syncthreads();

        const unsigned stoff = (c & 1) * SA_STAGE;
        unsigned ah[4][4], al[4][4];
#pragma unroll
        for (int mf = 0; mf < 4; mf++) {
            unsigned a = aH0 + stoff + mf * 16 * (GST * 2);
            ldsm4(a, ah[mf][0], ah[mf][1], ah[mf][2], ah[mf][3]);
            ldsm4(a + SA_HL, al[mf][0], al[mf][1], al[mf][2], al[mf][3]);
        }
#pragma unroll
        for (int p = 0; p < 2; p++) {
            unsigned bh[4], bl[4];
            unsigned bb = bH0 + stoff + p * 16 * (GST * 2);
            ldsm4(bb, bh[0], bh[1], bh[2], bh[3]);
            ldsm4(bb + SA_HL, bl[0], bl[1], bl[2], bl[3]);
#pragma unroll
            for (int mf = 0; mf < 4; mf++) {
                mma16816(acc[mf][2 * p],     ah[mf][0], ah[mf][1], ah[mf][2], ah[mf][3], bh[0], bh[1]);
                mma16816(acc[mf][2 * p + 1], ah[mf][0], ah[mf][1], ah[mf][2], ah[mf][3], bh[2], bh[3]);
                mma16816(acc[mf][2 * p],     ah[mf][0], ah[mf][1], ah[mf][2], ah[mf][3], bl[0], bl[1]);
                mma16816(acc[mf][2 * p + 1], ah[mf][0], ah[mf][1], ah[mf][2], ah[mf][3], bl[2], bl[3]);
                mma16816(acc[mf][2 * p],     al[mf][0], al[mf][1], al[mf][2], al[mf][3], bh[0], bh[1]);
                mma16816(acc[mf][2 * p + 1], al[mf][0], al[mf][1], al[mf][2], al[mf][3], bh[2], bh[3]);
            }
        }
        __syncthreads();
    }

#pragma unroll
    for (int nf = 0; nf < 4; nf++) {
        int col = nw * 32 + nf * 8 + (lane & 3) * 2;
        float2 bb = *(const float2*)&bias[n0 + col];
#pragma unroll
        for (int mf = 0; mf < 4; mf++) {
            int row = m0 + mw * 64 + mf * 16 + (lane >> 2);
            float x0 = acc[mf][nf][0] + bb.x, y0 = acc[mf][nf][1] + bb.y;
            float x1 = acc[mf][nf][2] + bb.x, y1 = acc[mf][nf][3] + bb.y;
            if (SPLIT_OUT) {
                unsigned h0, l0, h1, l1;
                split2(x0, y0, h0, l0);
                split2(x1, y1, h1, l1);
                *(unsigned*)&Chi[(size_t)row * N + n0 + col] = h0;
                *(unsigned*)&Clo[(size_t)row * N + n0 + col] = l0;
                *(unsigned*)&Chi[(size_t)(row + 8) * N + n0 + col] = h1;
                *(unsigned*)&Clo[(size_t)(row + 8) * N + n0 + col] = l1;
            } else {
                *(float2*)&Cf[(size_t)row * N + n0 + col] = make_float2(x0, y0);
                *(float2*)&Cf[(size_t)(row + 8) * N + n0 + col] = make_float2(x1, y1);
            }
        }
    }
}

// ---------------------------------------------------------------------------
// Tensor-core flash attention (R2 layout), epilogue writes split bf16 Ctx.
// ---------------------------------------------------------------------------
#define AST 72
#define ATTN_SMEM_BYTES (36864 * 2 + 256)

__global__ __launch_bounds__(256) void attn_tc(
    const __nv_bfloat16* __restrict__ Qhi, const __nv_bfloat16* __restrict__ Qlo,
    const __nv_bfloat16* __restrict__ Khi, const __nv_bfloat16* __restrict__ Klo,
    const __nv_bfloat16* __restrict__ Vhi, const __nv_bfloat16* __restrict__ Vlo,
    const float* __restrict__ W,
    __nv_bfloat16* __restrict__ Ctxhi, __nv_bfloat16* __restrict__ Ctxlo)
{
    extern __shared__ char smc[];
    __nv_bfloat16 (*sQh)[AST] = (__nv_bfloat16(*)[AST])(smc);
    __nv_bfloat16 (*sQl)[AST] = (__nv_bfloat16(*)[AST])(smc + 18432);
    __nv_bfloat16 (*sKh)[AST] = (__nv_bfloat16(*)[AST])(smc + 36864);
    __nv_bfloat16 (*sKl)[AST] = (__nv_bfloat16(*)[AST])(smc + 46080);
    __nv_bfloat16 (*sVh)[AST] = (__nv_bfloat16(*)[AST])(smc + 55296);
    __nv_bfloat16 (*sVl)[AST] = (__nv_bfloat16(*)[AST])(smc + 64512);
    float* ws = (float*)(smc + 73728);

    const int tid = threadIdx.x, lane = tid & 31, warp = tid >> 5;
    const int qt = blockIdx.x, h = blockIdx.y, b = blockIdx.z;

    const size_t qg = ((size_t)(b * T_SEQ + qt * 128)) * E_DIM + h * 64;
#pragma unroll
    for (int it = 0; it < 4; it++) {
        int i = tid + it * 256;
        int r = i >> 3, c = (i & 7) * 8;
        *(uint4*)&sQh[r][c] = *(const uint4*)&Qhi[qg + (size_t)r * E_DIM + c];
        *(uint4*)&sQl[r][c] = *(const uint4*)&Qlo[qg + (size_t)r * E_DIM + c];
    }

    const int arow = warp * 16 + (lane & 15);
    const int akoff = (lane >> 4) * 8;
    const unsigned aH = smem_u32(&sQh[arow][akoff]);
    const unsigned aL = smem_u32(&sQl[arow][akoff]);
    const int brow = (lane >> 4) * 8 + (lane & 7);
    const int bkoff = ((lane >> 3) & 1) * 8;
    const unsigned kH = smem_u32(&sKh[brow][bkoff]);
    const unsigned kL = smem_u32(&sKl[brow][bkoff]);
    const int vr = (lane & 7) + ((lane >> 3) & 1) * 8;
    const int vc = (lane >> 4) * 8;
    const unsigned vH = smem_u32(&sVh[vr][vc]);
    const unsigned vL = smem_u32(&sVl[vr][vc]);

    float o[8][4];
#pragma unroll
    for (int nf = 0; nf < 8; nf++)
#pragma unroll
        for (int j = 0; j < 4; j++) o[nf][j] = 0.f;
    float mA = -1e30f, mB = -1e30f, lA = 0.f, lB = 0.f;

    for (int kt = 0; kt < T_SEQ / 64; kt++) {
        __syncthreads();
        const size_t kg = ((size_t)(b * T_SEQ + kt * 64)) * E_DIM + h * 64;
#pragma unroll
        for (int it = 0; it < 2; it++) {
            int i = tid + it * 256;
            int r = i >> 3, c = (i & 7) * 8;
            size_t off = kg + (size_t)r * E_DIM + c;
            *(uint4*)&sKh[r][c] = *(const uint4*)&Khi[off];
            *(uint4*)&sKl[r][c] = *(const uint4*)&Klo[off];
            *(uint4*)&sVh[r][c] = *(const uint4*)&Vhi[off];
            *(uint4*)&sVl[r][c] = *(const uint4*)&Vlo[off];
        }
        if (tid < 64) ws[tid] = W[b * T_SEQ + kt * 64 + tid];
        __syncthreads();

        float s[8][4];
#pragma unroll
        for (int nf = 0; nf < 8; nf++)
#pragma unroll
            for (int j = 0; j < 4; j++) s[nf][j] = 0.f;

#pragma unroll
        for (int kc = 0; kc < 4; kc++) {
            unsigned ah[4], al[4];
            ldsm4(aH + kc * 32, ah[0], ah[1], ah[2], ah[3]);
            ldsm4(aL + kc * 32, al[0], al[1], al[2], al[3]);
#pragma unroll
            for (int g = 0; g < 4; g++) {
                unsigned bh[4], bl[4];
                ldsm4(kH + g * 2304 + kc * 32, bh[0], bh[1], bh[2], bh[3]);
                ldsm4(kL + g * 2304 + kc * 32, bl[0], bl[1], bl[2], bl[3]);
                mma16816(s[2 * g],     ah[0], ah[1], ah[2], ah[3], bh[0], bh[1]);
                mma16816(s[2 * g + 1], ah[0], ah[1], ah[2], ah[3], bh[2], bh[3]);
                mma16816(s[2 * g],     ah[0], ah[1], ah[2], ah[3], bl[0], bl[1]);
                mma16816(s[2 * g + 1], ah[0], ah[1], ah[2], ah[3], bl[2], bl[3]);
                mma16816(s[2 * g],     al[0], al[1], al[2], al[3], bh[0], bh[1]);
                mma16816(s[2 * g + 1], al[0], al[1], al[2], al[3], bh[2], bh[3]);
            }
        }

#pragma unroll
        for (int nf = 0; nf < 8; nf++) {
            float2 wp = *(const float2*)&ws[nf * 8 + (lane & 3) * 2];
            float f0 = SCALE * wp.x * wp.x, f1 = SCALE * wp.y * wp.y;
            s[nf][0] = (wp.x < WEPS) ? -1e30f : s[nf][0] * f0;
            s[nf][1] = (wp.y < WEPS) ? -1e30f : s[nf][1] * f1;
            s[nf][2] = (wp.x < WEPS) ? -1e30f : s[nf][2] * f0;
            s[nf][3] = (wp.y < WEPS) ? -1e30f : s[nf][3] * f1;
        }

        float tmA = -1e30f, tmB = -1e30f;
#pragma unroll
        for (int nf = 0; nf < 8; nf++) {
            tmA = fmaxf(tmA, fmaxf(s[nf][0], s[nf][1]));
            tmB = fmaxf(tmB, fmaxf(s[nf][2], s[nf][3]));
        }
        tmA = fmaxf(tmA, __shfl_xor_sync(0xffffffffu, tmA, 1));
        tmA = fmaxf(tmA, __shfl_xor_sync(0xffffffffu, tmA, 2));
        tmB = fmaxf(tmB, __shfl_xor_sync(0xffffffffu, tmB, 1));
        tmB = fmaxf(tmB, __shfl_xor_sync(0xffffffffu, tmB, 2));
        float mnA = fmaxf(mA, tmA), mnB = fmaxf(mB, tmB);
        float alA = __expf(mA - mnA), alB = __expf(mB - mnB);

        float sumA = 0.f, sumB = 0.f;
#pragma unroll
        for (int nf = 0; nf < 8; nf++) {
            s[nf][0] = (s[nf][0] < -1e29f) ? 0.f : __expf(s[nf][0] - mnA);
            s[nf][1] = (s[nf][1] < -1e29f) ? 0.f : __expf(s[nf][1] - mnA);
            s[nf][2] = (s[nf][2] < -1e29f) ? 0.f : __expf(s[nf][2] - mnB);
            s[nf][3] = (s[nf][3] < -1e29f) ? 0.f : __expf(s[nf][3] - mnB);
            sumA += s[nf][0] + s[nf][1];
            sumB += s[nf][2] + s[nf][3];
        }
        sumA += __shfl_xor_sync(0xffffffffu, sumA, 1);
        sumA += __shfl_xor_sync(0xffffffffu, sumA, 2);
        sumB += __shfl_xor_sync(0xffffffffu, sumB, 1);
        sumB += __shfl_xor_sync(0xffffffffu, sumB, 2);
        lA = lA * alA + sumA;
        lB = lB * alB + sumB;
        mA = mnA; mB = mnB;
#pragma unroll
        for (int nf = 0; nf < 8; nf++) {
            o[nf][0] *= alA; o[nf][1] *= alA;
            o[nf][2] *= alB; o[nf][3] *= alB;
        }

        unsigned ph[4][4], pl[4][4];
#pragma unroll
        for (int kc = 0; kc < 4; kc++) {
            split2(s[2 * kc][0],     s[2 * kc][1],     ph[kc][0], pl[kc][0]);
            split2(s[2 * kc][2],     s[2 * kc][3],     ph[kc][1], pl[kc][1]);
            split2(s[2 * kc + 1][0], s[2 * kc + 1][1], ph[kc][2], pl[kc][2]);
            split2(s[2 * kc + 1][2], s[2 * kc + 1][3], ph[kc][3], pl[kc][3]);
        }

#pragma unroll
        for (int p = 0; p < 4; p++) {
#pragma unroll
            for (int kc = 0; kc < 4; kc++) {
                unsigned vh[4], vl[4];
                ldsm4t(vH + kc * 2304 + p * 32, vh[0], vh[1], vh[2], vh[3]);
                ldsm4t(vL + kc * 2304 + p * 32, vl[0], vl[1], vl[2], vl[3]);
                mma16816(o[2 * p],     ph[kc][0], ph[kc][1], ph[kc][2], ph[kc][3], vh[0], vh[1]);
                mma16816(o[2 * p + 1], ph[kc][0], ph[kc][1], ph[kc][2], ph[kc][3], vh[2], vh[3]);
                mma16816(o[2 * p],     ph[kc][0], ph[kc][1], ph[kc][2], ph[kc][3], vl[0], vl[1]);
                mma16816(o[2 * p + 1], ph[kc][0], ph[kc][1], ph[kc][2], ph[kc][3], vl[2], vl[3]);
                mma16816(o[2 * p],     pl[kc][0], pl[kc][1], pl[kc][2], pl[kc][3], vh[0], vh[1]);
                mma16816(o[2 * p + 1], pl[kc][0], pl[kc][1], pl[kc][2], pl[kc][3], vh[2], vh[3]);
            }
        }
    }

    // epilogue: write split ctx
    const int rA = qt * 128 + warp * 16 + (lane >> 2);
    const float invA = 1.f / lA, invB = 1.f / lB;
    const size_t ob = ((size_t)(b * T_SEQ)) * E_DIM + h * 64;
#pragma unroll
    for (int nf = 0; nf < 8; nf++) {
        int col = nf * 8 + (lane & 3) * 2;
        unsigned h0, l0, h1, l1;
        split2(o[nf][0] * invA, o[nf][1] * invA, h0, l0);
        split2(o[nf][2] * invB, o[nf][3] * invB, h1, l1);
        *(unsigned*)&Ctxhi[ob + (size_t)rA * E_DIM + col] = h0;
        *(unsigned*)&Ctxlo[ob + (size_t)rA * E_DIM + col] = l0;
        *(unsigned*)&Ctxhi[ob + (size_t)(rA + 8) * E_DIM + col] = h1;
        *(unsigned*)&Ctxlo[ob + (size_t)(rA + 8) * E_DIM + col] = l1;
    }
}

// ---------------------------------------------------------------------------
extern "C" void kernel_launch(void* const* d_in, const int* in_sizes, int n_in,
                              void* d_out, int out_size)
{
    const float* q  = (const float*)d_in[0];
    const float* k  = (const float*)d_in[1];
    const float* v  = (const float*)d_in[2];
    const float* wt = (const float*)d_in[3];
    const float* Wq = (const float*)d_in[4];
    const float* bq = (const float*)d_in[5];
    const float* Wk = (const float*)d_in[6];
    const float* bk = (const float*)d_in[7];
    const float* Wv = (const float*)d_in[8];
    const float* bv = (const float*)d_in[9];
    const float* Wo = (const float*)d_in[10];
    const float* bo = (const float*)d_in[11];

    __nv_bfloat16 *Qh, *Ql, *Kh, *Kl, *Vh, *Vl, *Ch, *Cl;
    __nv_bfloat16 *qh, *ql, *kh, *kl, *vh, *vl;
    __nv_bfloat16 *Wqh, *Wql, *Wkh, *Wkl, *Wvh, *Wvl, *Woh, *Wol;
    cudaGetSymbolAddress((void**)&Qh, g_Qhi);  cudaGetSymbolAddress((void**)&Ql, g_Qlo);
    cudaGetSymbolAddress((void**)&Kh, g_Khi);  cudaGetSymbolAddress((void**)&Kl, g_Klo);
    cudaGetSymbolAddress((void**)&Vh, g_Vhi);  cudaGetSymbolAddress((void**)&Vl, g_Vlo);
    cudaGetSymbolAddress((void**)&Ch, g_Chi);  cudaGetSymbolAddress((void**)&Cl, g_Clo);
    cudaGetSymbolAddress((void**)&qh, g_qhi);  cudaGetSymbolAddress((void**)&ql, g_qlo);
    cudaGetSymbolAddress((void**)&kh, g_khi);  cudaGetSymbolAddress((void**)&kl, g_klo);
    cudaGetSymbolAddress((void**)&vh, g_vhi);  cudaGetSymbolAddress((void**)&vl, g_vlo);
    cudaGetSymbolAddress((void**)&Wqh, g_Wqh); cudaGetSymbolAddress((void**)&Wql, g_Wql);
    cudaGetSymbolAddress((void**)&Wkh, g_Wkh); cudaGetSymbolAddress((void**)&Wkl, g_Wkl);
    cudaGetSymbolAddress((void**)&Wvh, g_Wvh); cudaGetSymbolAddress((void**)&Wvl, g_Wvl);
    cudaGetSymbolAddress((void**)&Woh, g_Woh); cudaGetSymbolAddress((void**)&Wol, g_Wol);

    cudaFuncSetAttribute(attn_tc, cudaFuncAttributeMaxDynamicSharedMemorySize,
                         ATTN_SMEM_BYTES);
    cudaFuncSetAttribute(gemm_splitin<true>, cudaFuncAttributeMaxDynamicSharedMemorySize,
                         GEMM_SMEM);
    cudaFuncSetAttribute(gemm_splitin<false>, cudaFuncAttributeMaxDynamicSharedMemorySize,
                         GEMM_SMEM);

    const int M = BATCH * T_SEQ;
    const int N = E_DIM, K = E_DIM;
    const int nAct = M * E_DIM;       // 4 Mi elems
    const int nW = E_DIM * E_DIM;     // 1 Mi elems

    // pre-split pass
    split_kernel<<<nAct / 1024, 256>>>(q, qh, ql, nAct);
    split_kernel<<<nAct / 1024, 256>>>(k, kh, kl, nAct);
    split_kernel<<<nAct / 1024, 256>>>(v, vh, vl, nAct);
    split_kernel<<<nW / 1024, 256>>>(Wq, Wqh, Wql, nW);
    split_kernel<<<nW / 1024, 256>>>(Wk, Wkh, Wkl, nW);
    split_kernel<<<nW / 1024, 256>>>(Wv, Wvh, Wvl, nW);
    split_kernel<<<nW / 1024, 256>>>(Wo, Woh, Wol, nW);

    dim3 gg(N / 128, M / 128);   // (8, 32)
    gemm_splitin<true><<<gg, 256, GEMM_SMEM>>>(qh, ql, Wqh, Wql, bq, nullptr, Qh, Ql, M, N, K);
    gemm_splitin<true><<<gg, 256, GEMM_SMEM>>>(kh, kl, Wkh, Wkl, bk, nullptr, Kh, Kl, M, N, K);
    gemm_splitin<true><<<gg, 256, GEMM_SMEM>>>(vh, vl, Wvh, Wvl, bv, nullptr, Vh, Vl, M, N, K);

    dim3 ga(T_SEQ / 128, N_HEAD, BATCH);  // (8, 16, 4)
    attn_tc<<<ga, 256, ATTN_SMEM_BYTES>>>(Qh, Ql, Kh, Kl, Vh, Vl, wt, Ch, Cl);

    gemm_splitin<false><<<gg, 256, GEMM_SMEM>>>(Ch, Cl, Woh, Wol, bo, (float*)d_out,
                                                nullptr, nullptr, M, N, K);
}